// round 2
// baseline (speedup 1.0000x reference)
#include <cuda_runtime.h>
#include <math.h>

#define MAXN 50000
#define MAXE 800000
#define DIM  128

typedef unsigned long long ull;

// ---- scratch (static __device__ arrays; no allocation allowed) ----
__device__ float g_q   [MAXN * DIM];
__device__ float g_k   [MAXN * DIM];
__device__ float g_v   [MAXN * DIM];
__device__ float g_skip[MAXN * DIM];
__device__ float g_qwe [MAXN * 2 * DIM];   // [N][h*128+d]
__device__ float g_z   [MAXN * 2 * DIM];   // [N][h*128+d]
__device__ float g_vagg[MAXN * DIM];
__device__ float g_pre [MAXN * DIM];
__device__ int   g_counts [MAXN];
__device__ int   g_cursor [MAXN];
__device__ int   g_offsets[MAXN + 1];
__device__ int   g_perm   [MAXE];

// ------------------------------------------------------------------
__device__ __forceinline__ void ffma2(ull &d, ull a, ull b) {
    asm("fma.rn.f32x2 %0, %1, %2, %0;" : "+l"(d) : "l"(a), "l"(b));
}
__device__ __forceinline__ float lo32(ull v) { union { ull u; float2 f; } c; c.u = v; return c.f.x; }
__device__ __forceinline__ float hi32(ull v) { union { ull u; float2 f; } c; c.u = v; return c.f.y; }

// ------------------------------------------------------------------
__global__ void zero_kernel(int* a, int* b, int n) {
    int i = blockIdx.x * blockDim.x + threadIdx.x;
    if (i < n) { a[i] = 0; b[i] = 0; }
}

__global__ void count_kernel(const int* __restrict__ dst, int* __restrict__ counts, int e) {
    int i = blockIdx.x * blockDim.x + threadIdx.x;
    if (i < e) atomicAdd(&counts[dst[i]], 1);
}

// single-block scan over n counts -> exclusive offsets, offsets[n] = total
__global__ void scan_kernel(const int* __restrict__ counts, int* __restrict__ offsets, int n) {
    __shared__ int part[1024];
    int tid = threadIdx.x;
    int ch = (n + 1023) >> 10;
    int b = tid * ch;
    int eidx = b + ch; if (eidx > n) eidx = n;
    int s = 0;
    for (int i = b; i < eidx; i++) s += counts[i];
    part[tid] = s;
    __syncthreads();
    for (int off = 1; off < 1024; off <<= 1) {
        int v = (tid >= off) ? part[tid - off] : 0;
        __syncthreads();
        part[tid] += v;
        __syncthreads();
    }
    int excl = (tid == 0) ? 0 : part[tid - 1];
    for (int i = b; i < eidx; i++) { offsets[i] = excl; excl += counts[i]; }
    if (tid == 1023) offsets[n] = part[1023];
}

__global__ void scatter_kernel(const int* __restrict__ dst, const int* __restrict__ offsets,
                               int* __restrict__ cursor, int* __restrict__ perm, int e) {
    int i = blockIdx.x * blockDim.x + threadIdx.x;
    if (i < e) {
        int d = dst[i];
        int pos = offsets[d] + atomicAdd(&cursor[d], 1);
        perm[pos] = i;
    }
}

// ------------------------------------------------------------------
// Generic tiled GEMM with packed f32x2 FMA.
// C[n0+row][cOff+col] (+= is full overwrite) =
//      sum_{kk<K} A[(n0+row)*ldA + aOff + kk] * Bval(kk, col)
//    + bias[cOff+col]  (if bias)
//    + add0[(n0+row)*ldAdd + cOff+col] + add1[...]   (if non-null)
// Bval(kk,col) = transB ? B[(bRow+col)*ldB + bCol + kk]
//                       : B[(bRow+kk)*ldB + bCol + col]
// Block: 64 rows x N cols, 256 threads. K multiple of 32.
template<int N>
__global__ void gemm_p(const float* __restrict__ A, int ldA, int aOff,
                       const float* __restrict__ B, int ldB, int bRow, int bCol,
                       int K,
                       const float* __restrict__ bias,
                       const float* __restrict__ add0, const float* __restrict__ add1, int ldAdd,
                       float* __restrict__ C, int ldC, int cOff, int M, int transB) {
    constexpr int COLT  = N / 4;        // threads along cols
    constexpr int ROWT  = 256 / COLT;   // threads along rows
    constexpr int RPT   = 64 / ROWT;    // rows per thread
    constexpr int PAIRS = RPT / 2;

    __shared__ float  xs[32][68];       // A chunk transposed [k][row], padded
    __shared__ float2 ws2[32][N];       // W chunk, duplicated (w,w)

    const int tid = threadIdx.x;
    const int y = tid % ROWT;           // row group
    const int x = tid / ROWT;           // col group
    const int n0 = blockIdx.x * 64;

    ull acc[PAIRS][4];
#pragma unroll
    for (int p = 0; p < PAIRS; p++)
#pragma unroll
        for (int c = 0; c < 4; c++) acc[p][c] = 0ull;

    for (int kc = 0; kc < K; kc += 32) {
        __syncthreads();
        // ---- stage A chunk (transposed) ----
        {
            int r = tid >> 2, kq = tid & 3;
#pragma unroll
            for (int hh = 0; hh < 2; hh++) {
                int kk = kq * 4 + hh * 16;
                float4 av = make_float4(0.f, 0.f, 0.f, 0.f);
                if (n0 + r < M)
                    av = *(const float4*)&A[(size_t)(n0 + r) * ldA + aOff + kc + kk];
                xs[kk + 0][r] = av.x;
                xs[kk + 1][r] = av.y;
                xs[kk + 2][r] = av.z;
                xs[kk + 3][r] = av.w;
            }
        }
        // ---- stage B chunk (duplicated pairs) ----
        if (!transB) {
            int kk = tid >> 3, j0 = tid & 7;
#pragma unroll
            for (int m = 0; m < N / 8; m++) {
                int j = j0 + 8 * m;
                float w = B[(size_t)(bRow + kc + kk) * ldB + bCol + j];
                ws2[kk][j] = make_float2(w, w);
            }
        } else {
            int j = tid & (N - 1);
            int half = tid / N;                 // 256/N halves of kk range
            int kkpt = 32 / (256 / N);          // kk per thread
#pragma unroll
            for (int i = 0; i < 16; i++) {
                if (i >= kkpt) break;
                int kk = half * kkpt + i;
                float w = B[(size_t)(bRow + j) * ldB + bCol + kc + kk];
                ws2[kk][j] = make_float2(w, w);
            }
        }
        __syncthreads();
        // ---- compute ----
#pragma unroll 8
        for (int k = 0; k < 32; k++) {
            ull ap[PAIRS];
            if (PAIRS == 4) {
                ulonglong2 a0 = *(const ulonglong2*)&xs[k][RPT * y];
                ulonglong2 a1 = *(const ulonglong2*)&xs[k][RPT * y + 4];
                ap[0] = a0.x; ap[1] = a0.y;
                ap[PAIRS - 2] = a1.x; ap[PAIRS - 1] = a1.y;
            } else {
                ulonglong2 a0 = *(const ulonglong2*)&xs[k][RPT * y];
                ap[0] = a0.x; ap[PAIRS - 1] = a0.y;
            }
            ulonglong2 wA = *(const ulonglong2*)&ws2[k][4 * x];
            ulonglong2 wB = *(const ulonglong2*)&ws2[k][4 * x + 2];
            ull wv0 = wA.x, wv1 = wA.y, wv2 = wB.x, wv3 = wB.y;
#pragma unroll
            for (int p = 0; p < PAIRS; p++) {
                ffma2(acc[p][0], ap[p], wv0);
                ffma2(acc[p][1], ap[p], wv1);
                ffma2(acc[p][2], ap[p], wv2);
                ffma2(acc[p][3], ap[p], wv3);
            }
        }
    }

    // ---- epilogue ----
    float bj0 = 0.f, bj1 = 0.f, bj2 = 0.f, bj3 = 0.f;
    if (bias) {
        bj0 = bias[cOff + 4 * x + 0];
        bj1 = bias[cOff + 4 * x + 1];
        bj2 = bias[cOff + 4 * x + 2];
        bj3 = bias[cOff + 4 * x + 3];
    }
#pragma unroll
    for (int p = 0; p < PAIRS; p++) {
#pragma unroll
        for (int half = 0; half < 2; half++) {
            int row = RPT * y + 2 * p + half;
            if (n0 + row >= M) continue;
            float4 o;
            if (half == 0) o = make_float4(lo32(acc[p][0]), lo32(acc[p][1]),
                                           lo32(acc[p][2]), lo32(acc[p][3]));
            else           o = make_float4(hi32(acc[p][0]), hi32(acc[p][1]),
                                           hi32(acc[p][2]), hi32(acc[p][3]));
            o.x += bj0; o.y += bj1; o.z += bj2; o.w += bj3;
            size_t abase = (size_t)(n0 + row) * ldAdd + cOff + 4 * x;
            if (add0) {
                float4 a = *(const float4*)&add0[abase];
                o.x += a.x; o.y += a.y; o.z += a.z; o.w += a.w;
            }
            if (add1) {
                float4 a = *(const float4*)&add1[abase];
                o.x += a.x; o.y += a.y; o.z += a.z; o.w += a.w;
            }
            *(float4*)&C[(size_t)(n0 + row) * ldC + cOff + 4 * x] = o;
        }
    }
}

// ------------------------------------------------------------------
// warp-per-node online-softmax aggregation (index chain prefetched 1 ahead)
__global__ void attn_kernel(const int* __restrict__ src_arr, const int* __restrict__ offsets,
                            const int* __restrict__ perm,
                            const float* __restrict__ q, const float* __restrict__ k,
                            const float* __restrict__ v, const float* __restrict__ qwe,
                            const float* __restrict__ edge_attr,
                            float* __restrict__ z, float* __restrict__ vagg, int n) {
    int warp = (blockIdx.x * blockDim.x + threadIdx.x) >> 5;
    int lane = threadIdx.x & 31;
    if (warp >= n) return;
    const int i = warp;
    const int beg = offsets[i], end = offsets[i + 1];
    const int head = lane >> 4;

    float4 q4 = *(const float4*)&q  [(size_t)i * 128 + lane * 4];
    float4 w0 = *(const float4*)&qwe[(size_t)i * 256 + lane * 4];
    float4 w1 = *(const float4*)&qwe[(size_t)i * 256 + 128 + lane * 4];

    float m0 = -1e30f, m1 = -1e30f, l0 = 0.f, l1 = 0.f;
    float4 az0 = make_float4(0.f, 0.f, 0.f, 0.f);
    float4 az1 = az0;
    float4 av  = az0;

    int ecur = 0, scur = 0;
    if (beg < end) { ecur = perm[beg]; scur = src_arr[ecur]; }

    for (int t = beg; t < end; t++) {
        int enx = 0, snx = 0;
        if (t + 1 < end) { enx = perm[t + 1]; snx = src_arr[enx]; }
        int e = ecur, s = scur;
        float4 ea = *(const float4*)&edge_attr[(size_t)e * 128 + lane * 4];
        float4 k4 = *(const float4*)&k[(size_t)s * 128 + lane * 4];
        float4 v4 = *(const float4*)&v[(size_t)s * 128 + lane * 4];
        ecur = enx; scur = snx;

        float pqk = q4.x * k4.x + q4.y * k4.y + q4.z * k4.z + q4.w * k4.w;
        float p0  = ea.x * w0.x + ea.y * w0.y + ea.z * w0.z + ea.w * w0.w;
        float p1  = ea.x * w1.x + ea.y * w1.y + ea.z * w1.z + ea.w * w1.w;
#pragma unroll
        for (int off = 8; off; off >>= 1) pqk += __shfl_xor_sync(0xffffffffu, pqk, off);
#pragma unroll
        for (int off = 16; off; off >>= 1) {
            p0 += __shfl_xor_sync(0xffffffffu, p0, off);
            p1 += __shfl_xor_sync(0xffffffffu, p1, off);
        }
        float qko = __shfl_xor_sync(0xffffffffu, pqk, 16);
        float qk0 = head ? qko : pqk;
        float qk1 = head ? pqk : qko;
        float a0 = (qk0 + p0) * 0.125f;
        float a1 = (qk1 + p1) * 0.125f;

        float nm0 = fmaxf(m0, a0);
        float sc0 = __expf(m0 - nm0);
        float e0  = __expf(a0 - nm0);
        l0 = l0 * sc0 + e0; m0 = nm0;
        float nm1 = fmaxf(m1, a1);
        float sc1 = __expf(m1 - nm1);
        float e1  = __expf(a1 - nm1);
        l1 = l1 * sc1 + e1; m1 = nm1;

        az0.x = az0.x * sc0 + e0 * ea.x; az0.y = az0.y * sc0 + e0 * ea.y;
        az0.z = az0.z * sc0 + e0 * ea.z; az0.w = az0.w * sc0 + e0 * ea.w;
        az1.x = az1.x * sc1 + e1 * ea.x; az1.y = az1.y * sc1 + e1 * ea.y;
        az1.z = az1.z * sc1 + e1 * ea.z; az1.w = az1.w * sc1 + e1 * ea.w;
        float sch = head ? sc1 : sc0;
        float eh  = head ? e1  : e0;
        av.x = av.x * sch + eh * v4.x; av.y = av.y * sch + eh * v4.y;
        av.z = av.z * sch + eh * v4.z; av.w = av.w * sch + eh * v4.w;
    }

    float il0 = (end > beg) ? 1.f / l0 : 0.f;
    float il1 = (end > beg) ? 1.f / l1 : 0.f;
    float4 o0 = make_float4(az0.x * il0, az0.y * il0, az0.z * il0, az0.w * il0);
    float4 o1 = make_float4(az1.x * il1, az1.y * il1, az1.z * il1, az1.w * il1);
    *(float4*)&z[(size_t)i * 256 + lane * 4]       = o0;
    *(float4*)&z[(size_t)i * 256 + 128 + lane * 4] = o1;
    float ilh = head ? il1 : il0;
    float4 ov = make_float4(av.x * ilh, av.y * ilh, av.z * ilh, av.w * ilh);
    *(float4*)&vagg[(size_t)i * 128 + lane * 4] = ov;
}

// ------------------------------------------------------------------
extern "C" void kernel_launch(void* const* d_in, const int* in_sizes, int n_in,
                              void* d_out, int out_size) {
    const float* x     = (const float*)d_in[0];
    const float* eattr = (const float*)d_in[1];
    const float* Wq    = (const float*)d_in[2];
    const float* bq    = (const float*)d_in[3];
    const float* Wk    = (const float*)d_in[4];
    const float* bk    = (const float*)d_in[5];
    const float* Wv    = (const float*)d_in[6];
    const float* bv    = (const float*)d_in[7];
    const float* We    = (const float*)d_in[8];
    const float* Wskip = (const float*)d_in[9];
    const float* bskip = (const float*)d_in[10];
    const float* Wproj = (const float*)d_in[11];
    const float* bproj = (const float*)d_in[12];
    const int*   ei    = (const int*)d_in[13];

    const int n = in_sizes[0] / DIM;       // 50000
    const int e = in_sizes[1] / DIM;       // 800000
    const int* src = ei;                   // edge_index[0]
    const int* dst = ei + e;               // edge_index[1]

    float *pq, *pk, *pv, *pskip, *pqwe, *pz, *pvagg, *ppre;
    int *pcnt, *pcur, *poff, *pperm;
    cudaGetSymbolAddress((void**)&pq,    g_q);
    cudaGetSymbolAddress((void**)&pk,    g_k);
    cudaGetSymbolAddress((void**)&pv,    g_v);
    cudaGetSymbolAddress((void**)&pskip, g_skip);
    cudaGetSymbolAddress((void**)&pqwe,  g_qwe);
    cudaGetSymbolAddress((void**)&pz,    g_z);
    cudaGetSymbolAddress((void**)&pvagg, g_vagg);
    cudaGetSymbolAddress((void**)&ppre,  g_pre);
    cudaGetSymbolAddress((void**)&pcnt,  g_counts);
    cudaGetSymbolAddress((void**)&pcur,  g_cursor);
    cudaGetSymbolAddress((void**)&poff,  g_offsets);
    cudaGetSymbolAddress((void**)&pperm, g_perm);

    const int gb = (n + 63) / 64;          // 64-row GEMM blocks

    // CSR build
    zero_kernel<<<(n + 255) / 256, 256>>>(pcnt, pcur, n);
    count_kernel<<<(e + 255) / 256, 256>>>(dst, pcnt, e);
    scan_kernel<<<1, 1024>>>(pcnt, poff, n);
    scatter_kernel<<<(e + 255) / 256, 256>>>(dst, poff, pcur, pperm, e);

    // node projections: C = x @ W + b
    gemm_p<128><<<gb, 256>>>(x, DIM, 0, Wq,    DIM, 0, 0, DIM, bq,    nullptr, nullptr, 0, pq,    DIM, 0, n, 0);
    gemm_p<128><<<gb, 256>>>(x, DIM, 0, Wk,    DIM, 0, 0, DIM, bk,    nullptr, nullptr, 0, pk,    DIM, 0, n, 0);
    gemm_p<128><<<gb, 256>>>(x, DIM, 0, Wv,    DIM, 0, 0, DIM, bv,    nullptr, nullptr, 0, pv,    DIM, 0, n, 0);
    gemm_p<128><<<gb, 256>>>(x, DIM, 0, Wskip, DIM, 0, 0, DIM, bskip, nullptr, nullptr, 0, pskip, DIM, 0, n, 0);

    // qwe[n][h*128+d] = sum_c q[n][h*64+c] * We[d][h*64+c]   (B transposed)
    gemm_p<128><<<gb, 256>>>(pq, DIM, 0,  We, DIM, 0, 0,  64, nullptr, nullptr, nullptr, 0, pqwe, 256, 0,   n, 1);
    gemm_p<128><<<gb, 256>>>(pq, DIM, 64, We, DIM, 0, 64, 64, nullptr, nullptr, nullptr, 0, pqwe, 256, 128, n, 1);

    // edge aggregation (warp per node, online softmax)
    attn_kernel<<<(n * 32 + 255) / 256, 256>>>(src, poff, pperm, pq, pk, pv, pqwe, eattr, pz, pvagg, n);

    // pre[:, h*64:(h+1)*64] = z[:, h*128:(h+1)*128] @ We[:, h*64:] + vagg + skip
    gemm_p<64><<<gb, 256>>>(pz, 256, 0,   We, DIM, 0, 0,  DIM, nullptr, pvagg, pskip, DIM, ppre, DIM, 0,  n, 0);
    gemm_p<64><<<gb, 256>>>(pz, 256, 128, We, DIM, 0, 64, DIM, nullptr, pvagg, pskip, DIM, ppre, DIM, 64, n, 0);

    // out = pre @ Wproj + bproj
    gemm_p<128><<<gb, 256>>>(ppre, DIM, 0, Wproj, DIM, 0, 0, DIM, bproj, nullptr, nullptr, 0, (float*)d_out, DIM, 0, n, 0);
}